// round 10
// baseline (speedup 1.0000x reference)
#include <cuda_runtime.h>
#include <cuda_bf16.h>
#include <cstdint>

typedef unsigned long long ull;
typedef unsigned int u32;

#define M_STEPS 8
#define RMAX 64
#define P_MAX 524288
#define NB_STEP 296
#define MAXBLK 640
#define DEPTH 4
#define CHUNK_POS 128
#define CHUNK_BYTES 16384
// fold inv_sqrt(HD)=0.5 and log2(e) into q: hot loop = dot + EX2 only
#define C_SCALE (0.5f * 1.4426950408889634f)

// ---------------------------------------------------------------------------
// g_kev: per position p, 8 contiguous 16B chunks (128 B):
//   chunk 0..3 = KE head h dims [8h..8h+7] (bf16), chunk 4..7 = V head h
// ---------------------------------------------------------------------------
__device__ __align__(128) uint4 g_kev[(size_t)P_MAX * 8];   // 64 MB
__device__ float g_qs[32];
__device__ float g_z[32];
__device__ float g_partials[MAXBLK * 36];
__device__ int   g_tick[M_STEPS];

// ---------------------------------------------------------------------------
// PTX helpers
// ---------------------------------------------------------------------------
__device__ __forceinline__ ull fma2(ull a, ull b, ull c) {
    ull d; asm("fma.rn.f32x2 %0, %1, %2, %3;" : "=l"(d) : "l"(a), "l"(b), "l"(c));
    return d;
}
__device__ __forceinline__ float2 unpack2(ull a) {
    float2 r; asm("mov.b64 {%0, %1}, %2;" : "=f"(r.x), "=f"(r.y) : "l"(a));
    return r;
}
__device__ __forceinline__ float bf_lo(u32 v) { return __uint_as_float(v << 16); }
__device__ __forceinline__ float bf_hi(u32 v) { return __uint_as_float(v & 0xFFFF0000u); }
__device__ __forceinline__ float ex2f(float x) {
    float y; asm("ex2.approx.ftz.f32 %0, %1;" : "=f"(y) : "f"(x)); return y;
}
__device__ __forceinline__ u32 smem_u32(const void* p) {
    return (u32)__cvta_generic_to_shared(p);
}
__device__ __forceinline__ void mbar_init(u32 addr, u32 count) {
    asm volatile("mbarrier.init.shared.b64 [%0], %1;" :: "r"(addr), "r"(count) : "memory");
}
__device__ __forceinline__ void mbar_expect_tx(u32 addr, u32 bytes) {
    asm volatile("mbarrier.arrive.expect_tx.shared.b64 _, [%0], %1;"
                 :: "r"(addr), "r"(bytes) : "memory");
}
__device__ __forceinline__ void mbar_wait(u32 addr, u32 parity) {
    asm volatile(
        "{\n\t"
        ".reg .pred P1;\n\t"
        "WAIT_LOOP_%=:\n\t"
        "mbarrier.try_wait.parity.acquire.cta.shared::cta.b64 P1, [%0], %1, 0x989680;\n\t"
        "@P1 bra.uni WAIT_DONE_%=;\n\t"
        "bra.uni WAIT_LOOP_%=;\n\t"
        "WAIT_DONE_%=:\n\t"
        "}"
        :: "r"(addr), "r"(parity) : "memory");
}
__device__ __forceinline__ void tma_bulk_1d(u32 dst_smem, const void* src, u32 bytes, u32 mbar) {
    asm volatile(
        "cp.async.bulk.shared::cta.global.mbarrier::complete_tx::bytes "
        "[%0], [%1], %2, [%3];"
        :: "r"(dst_smem), "l"(src), "r"(bytes), "r"(mbar) : "memory");
}
__device__ __forceinline__ void fence_proxy_async_shared() {
    asm volatile("fence.proxy.async.shared::cta;" ::: "memory");
}

// ---------------------------------------------------------------------------
// Precompute (FMA2, lane = output dim, W rows in registers)
// ---------------------------------------------------------------------------
__global__ __launch_bounds__(256) void precompute_kernel(
    const float* __restrict__ z_past,
    const float* __restrict__ Wk, const float* __restrict__ bk,
    const float* __restrict__ Wv, const float* __restrict__ bv,
    const float* __restrict__ rel, const int* __restrict__ posp,
    int P, int ntiles)
{
    extern __shared__ char dyn[];
    float* srel = (float*)dyn;                          // 129*32 f = 16512 B (rel + bk)
    float* sx   = (float*)(dyn + 16512);                // 8 warps * 1024 f = 32768 B
    uint4* sstg = (uint4*)(dyn + 16512 + 32768);        // 8 warps * 288 u4 = 36864 B

    int tid = threadIdx.x, wid = tid >> 5, lane = tid & 31;

    for (int i = tid; i < 129 * 32; i += 256) srel[i] = rel[i] + bk[i & 31];
    __syncthreads();

    ull wk2[16], wv2[16];
    const ull* Wkp = (const ull*)Wk;
    const ull* Wvp = (const ull*)Wv;
    #pragma unroll
    for (int j = 0; j < 16; j++) { wk2[j] = Wkp[lane * 16 + j]; wv2[j] = Wvp[lane * 16 + j]; }
    float bvl = bv[lane];

    int pos = P;
    if (posp) {
        int v = *posp;
        if (v > 0 && v < (1 << 28)) pos = v;
        else { float fv = __int_as_float(v); if (fv > 0.f && fv < 2.68e8f) pos = (int)fv; }
    }
    int dpos = pos - P + RMAX;

    float* mysx = sx + wid * 1024;
    uint4* myst = sstg + wid * 288;                      // row pitch 9 u4 (144 B)
    unsigned short* myst16 = (unsigned short*)myst;      // row pitch 72 ushort

    int gw = blockIdx.x * 8 + wid, nw = gridDim.x * 8;
    for (int t = gw; t < ntiles; t += nw) {
        const float4* src = (const float4*)z_past + (size_t)t * 256;
        float4* dst = (float4*)mysx;
        int vcnt = P - t * 32;
        #pragma unroll
        for (int j = 0; j < 8; j++) {
            int fi = j * 32 + lane;
            float4 val = make_float4(0.f, 0.f, 0.f, 0.f);
            if ((fi >> 3) < vcnt) val = src[fi];
            dst[fi] = val;
        }
        __syncwarp();

        #pragma unroll 1
        for (int p = 0; p < 32; p++) {
            const ull* x2 = (const ull*)mysx + p * 16;
            ull ak = 0ull, av = 0ull;
            #pragma unroll
            for (int j = 0; j < 16; j++) {
                ull xx = x2[j];
                ak = fma2(wk2[j], xx, ak);
                av = fma2(wv2[j], xx, av);
            }
            float2 fk = unpack2(ak), fv2 = unpack2(av);
            int gp = t * 32 + p;
            int idx = gp + dpos; idx = min(max(idx, 0), 2 * RMAX);
            float kk = fk.x + fk.y + srel[idx * 32 + lane];
            float vv = fv2.x + fv2.y + bvl;
            if (gp >= P) { kk = 0.f; vv = 0.f; }
            myst16[p * 72 + lane]      = __bfloat16_as_ushort(__float2bfloat16(kk));
            myst16[p * 72 + 32 + lane] = __bfloat16_as_ushort(__float2bfloat16(vv));
        }
        __syncwarp();

        // write-out: global uint4 (t*32+pos)*8 + piece
        uint4* out = g_kev + (size_t)t * 256;
        #pragma unroll
        for (int j = 0; j < 8; j++) {
            int c = j * 32 + lane;
            out[c] = myst[(c >> 3) * 9 + (c & 7)];
        }
        __syncwarp();
    }
}

// ---------------------------------------------------------------------------
// Init
// ---------------------------------------------------------------------------
__global__ void init_kernel(const float* __restrict__ cand,
                            const float* __restrict__ Wq,
                            const float* __restrict__ bq)
{
    __shared__ float sz[32];
    int i = threadIdx.x;   // 32 threads
    sz[i] = cand[i];
    __syncwarp();
    float q = bq[i];
    #pragma unroll
    for (int j = 0; j < 32; j++) q += Wq[i * 32 + j] * sz[j];
    g_z[i]  = sz[i];
    g_qs[i] = q * C_SCALE;
    if (i < M_STEPS) g_tick[i] = 0;
}

// ---------------------------------------------------------------------------
// Step: TMA bulk pipeline. Each block grid-strides over 16 KB chunks (128
// positions), DEPTH=4 smem ring; thread 0 issues cp.async.bulk per stage,
// 8 warps consume (piece-per-lane, conflict-free LDS.128).
// ---------------------------------------------------------------------------
__global__ __launch_bounds__(256, 2) void step_kernel(
    int nchunks, int P, int m,
    const float* __restrict__ Wo, const float* __restrict__ bo,
    const float* __restrict__ Wq, const float* __restrict__ bq,
    const float* __restrict__ coupling, const float* __restrict__ nscale,
    float* __restrict__ out_final, int out_elems)
{
    extern __shared__ __align__(128) char dsm[];        // DEPTH * 16384 B
    __shared__ __align__(8) ull mbar[DEPTH];
    __shared__ float sq[32];
    __shared__ float sred[8][36];
    __shared__ int   sIsLast;
    __shared__ float sgrp[7][36];
    __shared__ float red[36];
    __shared__ float sout[32], sz[32];

    int tid = threadIdx.x;
    int lane = tid & 31;
    int wid  = tid >> 5;

    if (tid < 32) sq[tid] = g_qs[tid];
    if (tid == 0) {
        #pragma unroll
        for (int d = 0; d < DEPTH; d++) mbar_init(smem_u32(&mbar[d]), 1);
    }
    __syncthreads();

    int piece = lane & 7;
    int pgrp  = lane >> 3;          // position within quad
    int isV   = (lane >> 2) & 1;    // piece >= 4

    float qreg[8];
    #pragma unroll
    for (int j = 0; j < 8; j++) qreg[j] = sq[(piece & 3) * 8 + j];

    float acc[8];
    #pragma unroll
    for (int j = 0; j < 8; j++) acc[j] = 0.f;
    float lsum = 0.f;

    // chunks for this block: c(i) = blockIdx.x + i*gridDim.x
    int nIter = 0;
    for (int c = blockIdx.x; c < nchunks; c += gridDim.x) nIter++;

    // prologue: fill up to DEPTH stages
    if (tid == 0) {
        int fill = nIter < DEPTH ? nIter : DEPTH;
        for (int j = 0; j < fill; j++) {
            int cj = blockIdx.x + j * gridDim.x;
            u32 mb = smem_u32(&mbar[j]);
            mbar_expect_tx(mb, CHUNK_BYTES);
            tma_bulk_1d(smem_u32(dsm + j * CHUNK_BYTES),
                        (const char*)g_kev + (size_t)cj * CHUNK_BYTES,
                        CHUNK_BYTES, mb);
        }
    }

    #define PROC(d, posi) do {                                                \
        float x0 = bf_lo(d.x), x1 = bf_hi(d.x);                               \
        float x2 = bf_lo(d.y), x3 = bf_hi(d.y);                               \
        float x4 = bf_lo(d.z), x5 = bf_hi(d.z);                               \
        float x6 = bf_lo(d.w), x7 = bf_hi(d.w);                               \
        float s = x0*qreg[0] + x1*qreg[1] + x2*qreg[2] + x3*qreg[3]           \
                + x4*qreg[4] + x5*qreg[5] + x6*qreg[6] + x7*qreg[7];          \
        float w = ex2f(s);                                                    \
        w = ((posi) < P) ? w : 0.f;                                           \
        float wv = __shfl_sync(0xffffffffu, w, lane & ~4);                    \
        if (isV) {                                                            \
            acc[0] += wv * x0; acc[1] += wv * x1;                             \
            acc[2] += wv * x2; acc[3] += wv * x3;                             \
            acc[4] += wv * x4; acc[5] += wv * x5;                             \
            acc[6] += wv * x6; acc[7] += wv * x7;                             \
        } else {                                                              \
            lsum += wv;                                                       \
        }                                                                     \
    } while (0)

    for (int i = 0; i < nIter; i++) {
        int b  = i & (DEPTH - 1);
        u32 ph = (u32)((i / DEPTH) & 1);
        int c  = blockIdx.x + i * gridDim.x;

        mbar_wait(smem_u32(&mbar[b]), ph);

        // consume: 8 warps x 4 quads; quad = 4 positions x 8 pieces = 512 B
        const char* buf = dsm + b * CHUNK_BYTES;
        int pbase = c * CHUNK_POS;
        #pragma unroll
        for (int qq = 0; qq < 4; qq++) {
            int lq = wid * 4 + qq;
            uint4 d = *(const uint4*)(buf + lq * 512 + pgrp * 128 + piece * 16);
            PROC(d, pbase + lq * 4 + pgrp);
        }

        __syncthreads();   // all reads of buffer b complete

        int j = i + DEPTH;
        if (j < nIter && tid == 0) {
            fence_proxy_async_shared();
            int cj = blockIdx.x + j * gridDim.x;
            u32 mb = smem_u32(&mbar[b]);
            mbar_expect_tx(mb, CHUNK_BYTES);
            tma_bulk_1d(smem_u32(dsm + b * CHUNK_BYTES),
                        (const char*)g_kev + (size_t)cj * CHUNK_BYTES,
                        CHUNK_BYTES, mb);
        }
    }
    #undef PROC

    // reduce across the 4 position-groups (lanes differing in bits 3,4)
    #pragma unroll
    for (int off = 8; off <= 16; off <<= 1) {
        #pragma unroll
        for (int j = 0; j < 8; j++)
            acc[j] += __shfl_xor_sync(0xffffffffu, acc[j], off);
        lsum += __shfl_xor_sync(0xffffffffu, lsum, off);
    }

    if (lane < 8) {
        if (lane >= 4) {
            #pragma unroll
            for (int j = 0; j < 8; j++) sred[wid][(lane - 4) * 8 + j] = acc[j];
        } else {
            sred[wid][32 + lane] = lsum;
        }
    }
    __syncthreads();
    if (tid < 36) {
        float ssum = 0.f;
        #pragma unroll
        for (int wb = 0; wb < 8; wb++) ssum += sred[wb][tid];
        g_partials[blockIdx.x * 36 + tid] = ssum;
    }

    // ticket election: last finishing block runs the finalize chain
    __threadfence();
    if (tid == 0) {
        int prev = atomicAdd(&g_tick[m], 1);
        sIsLast = (prev == (int)gridDim.x - 1);
    }
    __syncthreads();
    if (!sIsLast) return;

    int nblocks = gridDim.x;
    int chunk = (nblocks + 6) / 7;
    if (tid < 252) {
        int g = tid / 36, k = tid % 36;
        int b0 = g * chunk, b1 = min(b0 + chunk, nblocks);
        float s = 0.f;
        for (int b = b0; b < b1; b++) s += __ldcg(&g_partials[b * 36 + k]);
        sgrp[g][k] = s;
    }
    __syncthreads();
    if (tid < 36) {
        float s = 0.f;
        #pragma unroll
        for (int g = 0; g < 7; g++) s += sgrp[g][tid];
        red[tid] = s;
    }
    __syncthreads();
    if (tid < 32) sout[tid] = red[tid] / red[32 + (tid >> 3)];
    __syncthreads();

    if (tid < 32) {
        float mod = bo[tid];
        #pragma unroll
        for (int j = 0; j < 32; j++) mod += Wo[tid * 32 + j] * sout[j];
        float zz = g_z[tid] + coupling[m] * mod;

        // mish(x) = x * tanh(softplus(x)), elementwise on re & im
        float sp = (zz > 20.f) ? zz : log1pf(expf(zz));
        float mm = zz * tanhf(sp);

        // LayerNorm over even (real) / odd (imag) parity classes
        float s1 = mm, s2 = mm * mm;
        #pragma unroll
        for (int off = 2; off < 32; off <<= 1) {
            s1 += __shfl_xor_sync(0xffffffffu, s1, off);
            s2 += __shfl_xor_sync(0xffffffffu, s2, off);
        }
        float mu  = s1 * (1.f / 16.f);
        float var = s2 * (1.f / 16.f) - mu * mu;
        float ns  = 1.0f;
        if (nscale) {
            float nv = *nscale;
            if (isfinite(nv) && fabsf(nv) > 1e-6f && fabsf(nv) < 1e6f) ns = nv;
        }
        float zn = (mm - mu) / sqrtf(var + 1e-5f) * ns;

        sz[tid]  = zn;
        g_z[tid] = zn;
    }
    __syncwarp(0xffffffffu);
    if (tid < 32) {
        float qv = bq[tid];
        #pragma unroll
        for (int j = 0; j < 32; j++) qv += Wq[tid * 32 + j] * sz[j];
        g_qs[tid] = qv * C_SCALE;
    }
    if (out_final && tid < 16) {
        if (out_elems == 16) out_final[tid] = sz[2 * tid];           // Re(z)
        else { out_final[2 * tid] = sz[2 * tid]; if (2 * tid + 1 < out_elems) out_final[2 * tid + 1] = sz[2 * tid + 1]; }
    }
}

// ---------------------------------------------------------------------------
// Launch
// ---------------------------------------------------------------------------
extern "C" void kernel_launch(void* const* d_in, const int* in_sizes, int n_in,
                              void* d_out, int out_size)
{
    int idx32[8], n32 = 0;
    int idx1k[8], n1k = 0;
    int idx1[4],  n1  = 0;
    int idxRel = -1, idxCoup = -1, idxBig = -1;
    long long bigSize = 0;
    for (int i = 0; i < n_in; i++) {
        int s = in_sizes[i];
        if (s == 32) { if (n32 < 8) idx32[n32++] = i; }
        else if (s == 1024) { if (n1k < 8) idx1k[n1k++] = i; }
        else if (s == 4128) idxRel = i;
        else if (s == 8) idxCoup = i;
        else if (s == 1) { if (n1 < 4) idx1[n1++] = i; }
        else if ((long long)s > bigSize) { bigSize = s; idxBig = i; }
    }
    if (idxBig < 0 || idxRel < 0 || idxCoup < 0 || n32 < 5 || n1k < 4) return;

    const float *cand, *Wq, *bq, *Wk, *bk, *Wv, *bv, *Wo, *bo;
    bool insertion = idx32[0] < idx1k[0];
    if (insertion) {
        cand = (const float*)d_in[idx32[0]];
        bq   = (const float*)d_in[idx32[1]];
        bk   = (const float*)d_in[idx32[2]];
        bv   = (const float*)d_in[idx32[3]];
        bo   = (const float*)d_in[idx32[4]];
        Wq   = (const float*)d_in[idx1k[0]];
        Wk   = (const float*)d_in[idx1k[1]];
        Wv   = (const float*)d_in[idx1k[2]];
        Wo   = (const float*)d_in[idx1k[3]];
    } else {
        Wk   = (const float*)d_in[idx1k[0]];
        Wo   = (const float*)d_in[idx1k[1]];
        Wq   = (const float*)d_in[idx1k[2]];
        Wv   = (const float*)d_in[idx1k[3]];
        bk   = (const float*)d_in[idx32[0]];
        bo   = (const float*)d_in[idx32[1]];
        bq   = (const float*)d_in[idx32[2]];
        bv   = (const float*)d_in[idx32[3]];
        cand = (const float*)d_in[idx32[4]];
    }
    const float* rel  = (const float*)d_in[idxRel];
    const float* coup = (const float*)d_in[idxCoup];
    const float* nsc  = (n1 > 0) ? (const float*)d_in[idx1[0]] : nullptr;
    const int*   pos  = (n1 > 1) ? (const int*)d_in[idx1[1]] : nullptr;

    int P = in_sizes[idxBig] / 32;
    if (P > P_MAX) P = P_MAX;
    int PAD128 = (P + 127) & ~127;          // chunk-aligned padding
    int ntiles = PAD128 / 32;               // precompute zero-fills past P
    int nchunks = PAD128 / CHUNK_POS;

    static int smem_set = 0;
    const int PRE_SMEM  = 16512 + 32768 + 36864;   // 86144 B
    const int STEP_SMEM = DEPTH * CHUNK_BYTES;     // 65536 B
    if (!smem_set) {
        cudaFuncSetAttribute(precompute_kernel,
                             cudaFuncAttributeMaxDynamicSharedMemorySize, PRE_SMEM);
        cudaFuncSetAttribute(step_kernel,
                             cudaFuncAttributeMaxDynamicSharedMemorySize, STEP_SMEM);
        smem_set = 1;
    }

    precompute_kernel<<<148, 256, PRE_SMEM>>>((const float*)d_in[idxBig],
                                              Wk, bk, Wv, bv, rel, pos, P, ntiles);
    init_kernel<<<1, 32>>>(cand, Wq, bq);

    for (int m = 0; m < M_STEPS; m++) {
        step_kernel<<<NB_STEP, 256, STEP_SMEM>>>(nchunks, P, m, Wo, bo, Wq, bq, coup, nsc,
                                                 (m == M_STEPS - 1) ? (float*)d_out : nullptr,
                                                 out_size);
    }
}

// round 11
// speedup vs baseline: 1.1226x; 1.1226x over previous
#include <cuda_runtime.h>
#include <cuda_bf16.h>
#include <cstdint>

typedef unsigned long long ull;
typedef unsigned int u32;

#define M_STEPS 8
#define RMAX 64
#define P_MAX 524288
#define NGRID 148
#define NTHR 512
#define NWARPS 16
#define PARTW 132            // 4 heads x 32-dim numerator + 4 denominators
// fold inv_sqrt(HD)=0.5 and log2(e) into q (carried by a and ctab)
#define C_SCALE (0.5f * 1.4426950408889634f)

// ---------------------------------------------------------------------------
// Device globals (no allocations allowed)
// g_x: z_past in bf16, per position 4 chunks of 16B (8 bf16 each), natural
//      order: chunk index = p*4 + j, j covers dims [8j..8j+7].
// ---------------------------------------------------------------------------
__device__ __align__(128) uint4 g_x[(size_t)P_MAX * 4];   // 32 MB
__device__ float  g_qs[32];          // scaled q (diagnostic; a/ctab carry it)
__device__ float  g_z[32];
__device__ float  g_a[128];          // a[d*4+h] = sum_j qs[8h+j]*Wk[(8h+j)*32+d]
__device__ float4 g_ctab[129];       // ctab[idx] = per-head qs.(bk+rel[idx])
__device__ int    g_dpos;
__device__ float  g_partials[NGRID * PARTW];
__device__ int    g_tick[M_STEPS];

// ---------------------------------------------------------------------------
// helpers
// ---------------------------------------------------------------------------
__device__ __forceinline__ float bf_lo(u32 v) { return __uint_as_float(v << 16); }
__device__ __forceinline__ float bf_hi(u32 v) { return __uint_as_float(v & 0xFFFF0000u); }
__device__ __forceinline__ u32 packbf2(float lo, float hi) {
    u32 d; asm("cvt.rn.bf16x2.f32 %0, %1, %2;" : "=r"(d) : "f"(hi), "f"(lo));
    return d;
}
__device__ __forceinline__ float ex2f(float x) {
    float y; asm("ex2.approx.ftz.f32 %0, %1;" : "=f"(y) : "f"(x)); return y;
}

// ---------------------------------------------------------------------------
// Precompute: pack z_past (fp32) -> bf16 chunks, zero-fill [P, PAD)
// ---------------------------------------------------------------------------
__global__ __launch_bounds__(256) void pack_kernel(
    const float* __restrict__ z_past, int P, int nchunks)
{
    int i = blockIdx.x * 256 + threadIdx.x;
    if (i >= nchunks) return;
    int p = i >> 2, j = i & 3;
    uint4 o = make_uint4(0u, 0u, 0u, 0u);
    if (p < P) {
        const float4* src = (const float4*)z_past + (size_t)p * 8 + j * 2;
        float4 A = src[0], B = src[1];
        o.x = packbf2(A.x, A.y);
        o.y = packbf2(A.z, A.w);
        o.z = packbf2(B.x, B.y);
        o.w = packbf2(B.z, B.w);
    }
    g_x[i] = o;
}

// ---------------------------------------------------------------------------
// Shared per-step parameter computation: given sz (z state in smem),
// compute qs, then a and ctab. Called by init and by the fused finalize.
// ---------------------------------------------------------------------------
__device__ __forceinline__ void compute_step_params(
    int tid, const float* sz, float* sqs,
    const float* __restrict__ Wq, const float* __restrict__ bq,
    const float* __restrict__ Wk, const float* __restrict__ bk,
    const float* __restrict__ rel)
{
    if (tid < 32) {
        float qv = bq[tid];
        #pragma unroll
        for (int j = 0; j < 32; j++) qv += Wq[tid * 32 + j] * sz[j];
        sqs[tid] = qv * C_SCALE;
        g_qs[tid] = sqs[tid];
    }
    __syncthreads();
    // a[d*4+h]
    if (tid < 128) {
        int h = tid & 3, d = tid >> 2;
        float s = 0.f;
        #pragma unroll
        for (int j = 0; j < 8; j++) s += sqs[h * 8 + j] * Wk[(h * 8 + j) * 32 + d];
        g_a[d * 4 + h] = s;
    }
    // ctab: 516 entries
    for (int e = tid; e < 516; e += NTHR) {
        int idx = e >> 2, h = e & 3;
        float s = 0.f;
        #pragma unroll
        for (int j = 0; j < 8; j++) {
            int i = h * 8 + j;
            s += sqs[i] * (bk[i] + rel[idx * 32 + i]);
        }
        ((float*)g_ctab)[idx * 4 + h] = s;
    }
}

// ---------------------------------------------------------------------------
// Init: z = candidate; params for step 0; dpos; tickets
// ---------------------------------------------------------------------------
__global__ __launch_bounds__(NTHR) void init_kernel(
    const float* __restrict__ cand,
    const float* __restrict__ Wq, const float* __restrict__ bq,
    const float* __restrict__ Wk, const float* __restrict__ bk,
    const float* __restrict__ rel, const int* __restrict__ posp, int P)
{
    __shared__ float sz[32], sqs[32];
    int tid = threadIdx.x;
    if (tid < 32) { sz[tid] = cand[tid]; g_z[tid] = cand[tid]; }
    if (tid < M_STEPS) g_tick[tid] = 0;
    if (tid == 0) {
        int pos = P;
        if (posp) {
            int v = *posp;
            if (v > 0 && v < (1 << 28)) pos = v;
            else { float fv = __int_as_float(v); if (fv > 0.f && fv < 2.68e8f) pos = (int)fv; }
        }
        g_dpos = pos - P + RMAX;
    }
    __syncthreads();
    compute_step_params(tid, sz, sqs, Wq, bq, Wk, bk, rel);
}

// ---------------------------------------------------------------------------
// Step: stream x (bf16, 64 B/pos). Lane = (pg = lane>>2, piece = lane&3);
// piece holds dims [8p..8p+7]. Scores: per-lane partial dots + 2 shfl rounds.
// Accumulate per-head weighted x (numerators) in fp32. Fused finalize.
// ---------------------------------------------------------------------------
__global__ __launch_bounds__(NTHR, 1) void step_kernel(
    int ngroups, int P, int m,
    const float* __restrict__ Wo, const float* __restrict__ bo,
    const float* __restrict__ Wq, const float* __restrict__ bq,
    const float* __restrict__ Wk, const float* __restrict__ bk,
    const float* __restrict__ Wv, const float* __restrict__ bv,
    const float* __restrict__ rel,
    const float* __restrict__ coupling, const float* __restrict__ nscale,
    float* __restrict__ out_final, int out_elems)
{
    __shared__ float4 sctab[129];
    __shared__ float  sa[128];
    __shared__ float  sred[NWARPS][PARTW];
    __shared__ float  sgrp[3][PARTW];
    __shared__ float  red[PARTW];
    __shared__ float  sout[32], sz[32], sqs[32];
    __shared__ int    sIsLast;

    int tid  = threadIdx.x;
    int lane = tid & 31;
    int wid  = tid >> 5;
    int pg    = lane >> 2;       // position within group of 8
    int piece = lane & 3;        // which 8-dim slice of x

    if (tid < 129) sctab[tid] = g_ctab[tid];
    if (tid < 128) sa[tid] = g_a[tid];
    __syncthreads();

    int dpos = g_dpos;

    // per-lane score coefficients: ar[h][j] = a[(piece*8+j)*4+h]
    float ar[4][8];
    #pragma unroll
    for (int h = 0; h < 4; h++)
        #pragma unroll
        for (int j = 0; j < 8; j++)
            ar[h][j] = sa[(piece * 8 + j) * 4 + h];

    float acc[4][8];
    #pragma unroll
    for (int h = 0; h < 4; h++)
        #pragma unroll
        for (int j = 0; j < 8; j++) acc[h][j] = 0.f;
    float l[4] = {0.f, 0.f, 0.f, 0.f};

    int gw = blockIdx.x * NWARPS + wid;
    int nw = NGRID * NWARPS;

    #define PROC(d, gg) do {                                                  \
        float xx[8];                                                          \
        xx[0] = bf_lo(d.x); xx[1] = bf_hi(d.x);                               \
        xx[2] = bf_lo(d.y); xx[3] = bf_hi(d.y);                               \
        xx[4] = bf_lo(d.z); xx[5] = bf_hi(d.z);                               \
        xx[6] = bf_lo(d.w); xx[7] = bf_hi(d.w);                               \
        float s0 = 0.f, s1 = 0.f, s2 = 0.f, s3 = 0.f;                         \
        _Pragma("unroll")                                                     \
        for (int j = 0; j < 8; j++) {                                         \
            s0 += ar[0][j] * xx[j]; s1 += ar[1][j] * xx[j];                   \
            s2 += ar[2][j] * xx[j]; s3 += ar[3][j] * xx[j];                   \
        }                                                                     \
        s0 += __shfl_xor_sync(0xffffffffu, s0, 1);                            \
        s1 += __shfl_xor_sync(0xffffffffu, s1, 1);                            \
        s2 += __shfl_xor_sync(0xffffffffu, s2, 1);                            \
        s3 += __shfl_xor_sync(0xffffffffu, s3, 1);                            \
        s0 += __shfl_xor_sync(0xffffffffu, s0, 2);                            \
        s1 += __shfl_xor_sync(0xffffffffu, s1, 2);                            \
        s2 += __shfl_xor_sync(0xffffffffu, s2, 2);                            \
        s3 += __shfl_xor_sync(0xffffffffu, s3, 2);                            \
        int posi = (gg) * 8 + pg;                                             \
        int idx = min(max(posi + dpos, 0), 128);                              \
        float4 ct = sctab[idx];                                               \
        float w0 = ex2f(s0 + ct.x), w1 = ex2f(s1 + ct.y);                     \
        float w2 = ex2f(s2 + ct.z), w3 = ex2f(s3 + ct.w);                     \
        if (posi >= P) { w0 = 0.f; w1 = 0.f; w2 = 0.f; w3 = 0.f; }            \
        l[0] += w0; l[1] += w1; l[2] += w2; l[3] += w3;                       \
        _Pragma("unroll")                                                     \
        for (int j = 0; j < 8; j++) {                                         \
            acc[0][j] += w0 * xx[j]; acc[1][j] += w1 * xx[j];                 \
            acc[2][j] += w2 * xx[j]; acc[3][j] += w3 * xx[j];                 \
        }                                                                     \
    } while (0)

    // ngroups is even (PAD multiple of 16); U=2 groups per iteration
    for (int g = gw * 2; g < ngroups; g += nw * 2) {
        uint4 d0 = __ldg(g_x + (size_t)g * 32 + lane);
        uint4 d1 = __ldg(g_x + (size_t)g * 32 + 32 + lane);
        PROC(d0, g);
        PROC(d1, g + 1);
    }
    #undef PROC

    // reduce over the 8 position-groups (pg axis: xor offsets 4, 8, 16)
    #pragma unroll
    for (int off = 4; off <= 16; off <<= 1) {
        #pragma unroll
        for (int h = 0; h < 4; h++) {
            #pragma unroll
            for (int j = 0; j < 8; j++)
                acc[h][j] += __shfl_xor_sync(0xffffffffu, acc[h][j], off);
            l[h] += __shfl_xor_sync(0xffffffffu, l[h], off);
        }
    }
    // lanes 0-3 hold piece 0-3 sums; l identical on lanes 0-3
    if (lane < 4) {
        #pragma unroll
        for (int h = 0; h < 4; h++)
            #pragma unroll
            for (int j = 0; j < 8; j++)
                sred[wid][h * 32 + lane * 8 + j] = acc[h][j];
        if (lane == 0) {
            #pragma unroll
            for (int h = 0; h < 4; h++) sred[wid][128 + h] = l[h];
        }
    }
    __syncthreads();
    if (tid < PARTW) {
        float s = 0.f;
        #pragma unroll
        for (int wb = 0; wb < NWARPS; wb++) s += sred[wb][tid];
        g_partials[blockIdx.x * PARTW + tid] = s;
    }

    // ticket election: last finishing block runs finalize
    __threadfence();
    if (tid == 0) {
        int prev = atomicAdd(&g_tick[m], 1);
        sIsLast = (prev == NGRID - 1);
    }
    __syncthreads();
    if (!sIsLast) return;

    // merge 148 x 132 partials, 3-way split
    {
        const int CH = 50;
        if (tid < 3 * PARTW) {
            int c = tid / PARTW, k = tid % PARTW;
            int b0 = c * CH, b1 = min(b0 + CH, NGRID);
            float s = 0.f;
            #pragma unroll 4
            for (int b = b0; b < b1; b++) s += __ldcg(&g_partials[b * PARTW + k]);
            sgrp[c][k] = s;
        }
        __syncthreads();
        if (tid < PARTW) red[tid] = sgrp[0][tid] + sgrp[1][tid] + sgrp[2][tid];
        __syncthreads();
    }

    // out_i = sum_d Wv[i][d] * N_h[d]/L_h + bv_i,  h = i>>3
    if (tid < 32) {
        int h = tid >> 3;
        float invL = 1.f / red[128 + h];
        float s = 0.f;
        #pragma unroll
        for (int d = 0; d < 32; d++) s += Wv[tid * 32 + d] * red[h * 32 + d];
        sout[tid] = s * invL + bv[tid];
    }
    __syncthreads();

    if (tid < 32) {
        float mod = bo[tid];
        #pragma unroll
        for (int j = 0; j < 32; j++) mod += Wo[tid * 32 + j] * sout[j];
        float zz = g_z[tid] + coupling[m] * mod;

        // mish on re & im parts
        float sp = (zz > 20.f) ? zz : log1pf(expf(zz));
        float mm = zz * tanhf(sp);

        // LayerNorm over even/odd parity classes
        float s1 = mm, s2 = mm * mm;
        #pragma unroll
        for (int off = 2; off < 32; off <<= 1) {
            s1 += __shfl_xor_sync(0xffffffffu, s1, off);
            s2 += __shfl_xor_sync(0xffffffffu, s2, off);
        }
        float mu  = s1 * (1.f / 16.f);
        float var = s2 * (1.f / 16.f) - mu * mu;
        float ns  = 1.0f;
        if (nscale) {
            float nv = *nscale;
            if (isfinite(nv) && fabsf(nv) > 1e-6f && fabsf(nv) < 1e6f) ns = nv;
        }
        float zn = (mm - mu) / sqrtf(var + 1e-5f) * ns;
        sz[tid]  = zn;
        g_z[tid] = zn;
    }
    __syncthreads();

    // next step's q-dependent params
    compute_step_params(tid, sz, sqs, Wq, bq, Wk, bk, rel);

    if (out_final && tid < 16) {
        if (out_elems == 16) out_final[tid] = sz[2 * tid];           // Re(z)
        else { out_final[2 * tid] = sz[2 * tid]; if (2 * tid + 1 < out_elems) out_final[2 * tid + 1] = sz[2 * tid + 1]; }
    }
}

// ---------------------------------------------------------------------------
// Launch
// ---------------------------------------------------------------------------
extern "C" void kernel_launch(void* const* d_in, const int* in_sizes, int n_in,
                              void* d_out, int out_size)
{
    int idx32[8], n32 = 0;
    int idx1k[8], n1k = 0;
    int idx1[4],  n1  = 0;
    int idxRel = -1, idxCoup = -1, idxBig = -1;
    long long bigSize = 0;
    for (int i = 0; i < n_in; i++) {
        int s = in_sizes[i];
        if (s == 32) { if (n32 < 8) idx32[n32++] = i; }
        else if (s == 1024) { if (n1k < 8) idx1k[n1k++] = i; }
        else if (s == 4128) idxRel = i;
        else if (s == 8) idxCoup = i;
        else if (s == 1) { if (n1 < 4) idx1[n1++] = i; }
        else if ((long long)s > bigSize) { bigSize = s; idxBig = i; }
    }
    if (idxBig < 0 || idxRel < 0 || idxCoup < 0 || n32 < 5 || n1k < 4) return;

    const float *cand, *Wq, *bq, *Wk, *bk, *Wv, *bv, *Wo, *bo;
    bool insertion = idx32[0] < idx1k[0];
    if (insertion) {
        cand = (const float*)d_in[idx32[0]];
        bq   = (const float*)d_in[idx32[1]];
        bk   = (const float*)d_in[idx32[2]];
        bv   = (const float*)d_in[idx32[3]];
        bo   = (const float*)d_in[idx32[4]];
        Wq   = (const float*)d_in[idx1k[0]];
        Wk   = (const float*)d_in[idx1k[1]];
        Wv   = (const float*)d_in[idx1k[2]];
        Wo   = (const float*)d_in[idx1k[3]];
    } else {
        Wk   = (const float*)d_in[idx1k[0]];
        Wo   = (const float*)d_in[idx1k[1]];
        Wq   = (const float*)d_in[idx1k[2]];
        Wv   = (const float*)d_in[idx1k[3]];
        bk   = (const float*)d_in[idx32[0]];
        bo   = (const float*)d_in[idx32[1]];
        bq   = (const float*)d_in[idx32[2]];
        bv   = (const float*)d_in[idx32[3]];
        cand = (const float*)d_in[idx32[4]];
    }
    const float* rel  = (const float*)d_in[idxRel];
    const float* coup = (const float*)d_in[idxCoup];
    const float* nsc  = (n1 > 0) ? (const float*)d_in[idx1[0]] : nullptr;
    const int*   pos  = (n1 > 1) ? (const int*)d_in[idx1[1]] : nullptr;

    int P = in_sizes[idxBig] / 32;
    if (P > P_MAX) P = P_MAX;
    int PAD = (P + 15) & ~15;          // groups of 8, even group count
    int ngroups = PAD / 8;
    int nchunks = PAD * 4;

    pack_kernel<<<(nchunks + 255) / 256, 256>>>((const float*)d_in[idxBig], P, nchunks);
    init_kernel<<<1, NTHR>>>(cand, Wq, bq, Wk, bk, rel, pos, P);

    for (int m = 0; m < M_STEPS; m++) {
        step_kernel<<<NGRID, NTHR>>>(ngroups, P, m,
                                     Wo, bo, Wq, bq, Wk, bk, Wv, bv, rel,
                                     coup, nsc,
                                     (m == M_STEPS - 1) ? (float*)d_out : nullptr,
                                     out_size);
    }
}